// round 8
// baseline (speedup 1.0000x reference)
#include <cuda_runtime.h>
#include <cstdint>

// EquivariantLayerNorm: out = (covar + EPS*I)^{-1/2} @ (x - mean) * weight
// covar = xc @ xc^T / D + EPS*diag(1,2,3),  x: (N, 3, 256) fp32.
//
// R8: software-pipelined sample streams (attacks the DRAM 73% plateau).
//   Each 16-lane group owns ITERS consecutive samples and double-buffers
//   them through smem with cp.async: the load for sample i+1 is in flight
//   while sample i is reduced/solved/stored (cp.async.wait_group 1).
//   This breaks the load/compute phase oscillation that capped DRAM duty
//   cycle in R4-R7. Closed-form A^{-1/2} per lane; barrier-free.

#define ITERS 4

__device__ __forceinline__ void cp_async16(unsigned saddr, const void* gptr) {
    asm volatile("cp.async.cg.shared.global [%0], [%1], 16;"
                 :: "r"(saddr), "l"(gptr));
}

__device__ __forceinline__ float sum4(float4 a) {
    return (a.x + a.y) + (a.z + a.w);
}
__device__ __forceinline__ float dot4(float4 a, float4 b, float acc) {
    acc = fmaf(a.x, b.x, acc);
    acc = fmaf(a.y, b.y, acc);
    acc = fmaf(a.z, b.z, acc);
    acc = fmaf(a.w, b.w, acc);
    return acc;
}

__global__ void __launch_bounds__(128, 4) eqln_kernel(
    const float* __restrict__ in,
    const float* __restrict__ weight,
    float* __restrict__ out,
    int nSamples)
{
    __shared__ float smx[4][2][2][768];   // [warp][half][buf][elements]

    const int warp = threadIdx.x >> 5;    // 0..3
    const int lane = threadIdx.x & 31;
    const int half = lane >> 4;           // sample stream within warp
    const int hl   = lane & 15;           // lane within 16-lane group

    const long group = (long)blockIdx.x * 8 + warp * 2 + half;
    const long sbase = group * ITERS;     // first sample of this stream

    // weight held in registers across the whole loop
    const float4* __restrict__ w4p = (const float4*)weight;
    float4 wv[4];
    #pragma unroll
    for (int c = 0; c < 4; c++) wv[c] = __ldg(&w4p[c * 16 + hl]);

    unsigned sb0 = (unsigned)__cvta_generic_to_shared(&smx[warp][half][0][0]);
    unsigned sb1 = (unsigned)__cvta_generic_to_shared(&smx[warp][half][1][0]);

    // ---- prologue: issue loads for sample 0 ----
    {
        long ls = sbase < (long)nSamples ? sbase : (long)nSamples - 1;
        const char* g = (const char*)(in + ls * 768);
        #pragma unroll
        for (int c = 0; c < 12; c++) {
            int f4 = c * 16 + hl;
            cp_async16(sb0 + f4 * 16, g + (size_t)f4 * 16);
        }
        asm volatile("cp.async.commit_group;");
    }

    #pragma unroll
    for (int i = 0; i < ITERS; i++) {
        const long s = sbase + i;
        const unsigned sbuf = (i & 1) ? sb1 : sb0;

        // prefetch sample i+1 into the other buffer BEFORE waiting on i
        if (i + 1 < ITERS) {
            long ns = s + 1 < (long)nSamples ? s + 1 : (long)nSamples - 1;
            const unsigned nbuf = (i & 1) ? sb0 : sb1;
            const char* g = (const char*)(in + ns * 768);
            #pragma unroll
            for (int c = 0; c < 12; c++) {
                int f4 = c * 16 + hl;
                cp_async16(nbuf + f4 * 16, g + (size_t)f4 * 16);
            }
            asm volatile("cp.async.commit_group;");
            asm volatile("cp.async.wait_group 1;" ::: "memory");
        } else {
            asm volatile("cp.async.wait_group 0;" ::: "memory");
        }
        // each lane reads only the float4s it copied itself -> no sync needed

        const float4* sx = (const float4*)((i & 1) ? &smx[warp][half][1][0]
                                                   : &smx[warp][half][0][0]);

        // ---- 9-quantity reduction (row sums + raw second moments) ----
        float sm[9];
        #pragma unroll
        for (int q = 0; q < 9; q++) sm[q] = 0.0f;

        #pragma unroll
        for (int c = 0; c < 4; c++) {
            float4 a = sx[       c * 16 + hl];
            float4 b = sx[ 64 +  c * 16 + hl];
            float4 d = sx[128 +  c * 16 + hl];
            sm[0] += sum4(a);
            sm[1] += sum4(b);
            sm[2] += sum4(d);
            sm[3] = dot4(a, a, sm[3]);
            sm[4] = dot4(a, b, sm[4]);
            sm[5] = dot4(a, d, sm[5]);
            sm[6] = dot4(b, b, sm[6]);
            sm[7] = dot4(b, d, sm[7]);
            sm[8] = dot4(d, d, sm[8]);
        }

        // 4-level butterfly within the 16-lane group
        #pragma unroll
        for (int q = 0; q < 9; q++) {
            #pragma unroll
            for (int o = 8; o > 0; o >>= 1)
                sm[q] += __shfl_xor_sync(0xffffffffu, sm[q], o);
        }

        // ---- closed-form A^{-1/2} (redundant across the 16 lanes) ----
        const float invD = 1.0f / 256.0f;
        const float m0 = sm[0] * invD, m1 = sm[1] * invD, m2 = sm[2] * invD;

        const float a00 = fmaf(sm[3], invD, -m0 * m0) + 2.0e-3f;
        const float a01 = fmaf(sm[4], invD, -m0 * m1);
        const float a02 = fmaf(sm[5], invD, -m0 * m2);
        const float a11 = fmaf(sm[6], invD, -m1 * m1) + 3.0e-3f;
        const float a12 = fmaf(sm[7], invD, -m1 * m2);
        const float a22 = fmaf(sm[8], invD, -m2 * m2) + 4.0e-3f;

        // eigenvalues via trigonometric method (A >= 2e-3 I, roots positive)
        const float qm  = (a00 + a11 + a22) * (1.0f / 3.0f);
        const float d0 = a00 - qm, d1 = a11 - qm, d2 = a22 - qm;
        const float off2 = a01*a01 + a02*a02 + a12*a12;
        float p2 = (d0*d0 + d1*d1 + d2*d2) * (1.0f / 6.0f) + off2 * (1.0f / 3.0f);
        p2 = fmaxf(p2, 1.0e-24f);
        const float detB = d0 * (d1*d2 - a12*a12)
                         - a01 * (a01*d2 - a12*a02)
                         + a02 * (a01*a12 - d1*a02);
        const float ip  = rsqrtf(p2);
        float r = 0.5f * detB * (ip * ip * ip);
        r = fminf(fmaxf(r, -1.0f), 1.0f);
        const float phi = acosf(r) * (1.0f / 3.0f);
        const float twop = 2.0f * p2 * ip;
        const float l1 = qm + twop * __cosf(phi);
        const float l3 = qm + twop * __cosf(phi + 2.0943951f);
        const float l2 = 3.0f * qm - l1 - l3;

        // cancellation-free divided differences of 1/sqrt
        const float u = sqrtf(l1), v = sqrtf(l2), w = sqrtf(l3);
        const float uv = u + v, vw = v + w, uw = u + w;
        const float rden = 1.0f / ((u * v * w) * uv * vw * uw);
        const float c2 = (u + v + w) * rden;
        const float c1 = -(w * vw * uw) * rden;
        const float c0 = (v * w) * (vw * uv * uw) * rden;

        // S = c0*I + c1*(A-l1 I) + c2*(A-l1 I)(A-l2 I)
        const float e0 = a00 - l1, e1 = a11 - l1, e2 = a22 - l1;
        const float g0 = a00 - l2, g1 = a11 - l2, g2 = a22 - l2;
        const float P00 = e0*g0 + a01*a01 + a02*a02;
        const float P01 = a01*(e0 + g1) + a02*a12;
        const float P02 = a02*(e0 + g2) + a01*a12;
        const float P11 = a01*a01 + e1*g1 + a12*a12;
        const float P12 = a12*(e1 + g2) + a01*a02;
        const float P22 = a02*a02 + a12*a12 + e2*g2;

        const float S00 = fmaf(c2, P00, fmaf(c1, e0, c0));
        const float S01 = fmaf(c2, P01, c1 * a01);
        const float S02 = fmaf(c2, P02, c1 * a02);
        const float S11 = fmaf(c2, P11, fmaf(c1, e1, c0));
        const float S12 = fmaf(c2, P12, c1 * a12);
        const float S22 = fmaf(c2, P22, fmaf(c1, e2, c0));

        const float bb0 = -(S00*m0 + S01*m1 + S02*m2);
        const float bb1 = -(S01*m0 + S11*m1 + S12*m2);
        const float bb2 = -(S02*m0 + S12*m1 + S22*m2);

        // ---- fused epilogue ----
        if (s < (long)nSamples) {
            float4* __restrict__ xout = (float4*)(out + s * 768);
            #pragma unroll
            for (int c = 0; c < 4; c++) {
                float4 a = sx[       c * 16 + hl];
                float4 b = sx[ 64 +  c * 16 + hl];
                float4 d = sx[128 +  c * 16 + hl];
                float4 wq = wv[c];

                float4 o;
                o.x = fmaf(S00, a.x, fmaf(S01, b.x, fmaf(S02, d.x, bb0))) * wq.x;
                o.y = fmaf(S00, a.y, fmaf(S01, b.y, fmaf(S02, d.y, bb0))) * wq.y;
                o.z = fmaf(S00, a.z, fmaf(S01, b.z, fmaf(S02, d.z, bb0))) * wq.z;
                o.w = fmaf(S00, a.w, fmaf(S01, b.w, fmaf(S02, d.w, bb0))) * wq.w;
                __stcs(&xout[       c * 16 + hl], o);

                o.x = fmaf(S01, a.x, fmaf(S11, b.x, fmaf(S12, d.x, bb1))) * wq.x;
                o.y = fmaf(S01, a.y, fmaf(S11, b.y, fmaf(S12, d.y, bb1))) * wq.y;
                o.z = fmaf(S01, a.z, fmaf(S11, b.z, fmaf(S12, d.z, bb1))) * wq.z;
                o.w = fmaf(S01, a.w, fmaf(S11, b.w, fmaf(S12, d.w, bb1))) * wq.w;
                __stcs(&xout[ 64 +  c * 16 + hl], o);

                o.x = fmaf(S02, a.x, fmaf(S12, b.x, fmaf(S22, d.x, bb2))) * wq.x;
                o.y = fmaf(S02, a.y, fmaf(S12, b.y, fmaf(S22, d.y, bb2))) * wq.y;
                o.z = fmaf(S02, a.z, fmaf(S12, b.z, fmaf(S22, d.z, bb2))) * wq.z;
                o.w = fmaf(S02, a.w, fmaf(S12, b.w, fmaf(S22, d.w, bb2))) * wq.w;
                __stcs(&xout[128 +  c * 16 + hl], o);
            }
        }
    }
}

extern "C" void kernel_launch(void* const* d_in, const int* in_sizes, int n_in,
                              void* d_out, int out_size)
{
    const float* in = (const float*)d_in[0];
    const float* w  = (const float*)d_in[1];
    float* out      = (float*)d_out;

    int nSamples = in_sizes[0] / 768;               // N samples
    int groups   = (nSamples + ITERS - 1) / ITERS;  // 16-lane streams
    int grid     = (groups + 7) / 8;                // 8 streams per block
    eqln_kernel<<<grid, 128>>>(in, w, out, nSamples);
}